// round 1
// baseline (speedup 1.0000x reference)
#include <cuda_runtime.h>
#include <cuda_bf16.h>
#include <math.h>

// ---------------------------------------------------------------------------
// STTM: 4-layer transformer, w=192, C=128, NHEAD=4, hd=32
// feat layout everywhere: (w, n, C) row-major. Self: n in [0,256). fl: n<128, fr: n>=128.
// Key trick: rel-pos projections done on pos_enc (383 rows), gathered by d=191-i+j
// (or 191+i-j for the flipped table, since proj(pos_flip)[t] = proj(pos_enc)[382-t]).
// ---------------------------------------------------------------------------

#define W_ 192
#define CC 128
#define NB_SELF 256
#define NB_CROSS 128

// ------------------------- device scratch ---------------------------------
__device__ float g_ln [W_*NB_SELF*CC];        // LN output (self f2 / cross fl2|fr2)
__device__ float g_ln2[W_*NB_CROSS*CC];       // fr2n
__device__ float g_qkv[W_*NB_SELF*3*CC];      // self qkv; cross q @0, kv @ +192*128*128
__device__ float g_vo [W_*NB_SELF*CC];        // attention output
__device__ float g_proj[2*383*256];           // [0]: self layer proj, [1]: cross layer proj

// ------------------------- build feat from inputs -------------------------
// feat_left/right: (bs=2, C=128, hn0=64, w=192). fl[i, n=h*2+b, c] = FL[b,c,h,i]
__global__ void build_feat(const float* __restrict__ L, const float* __restrict__ R,
                           float* __restrict__ feat)
{
    __shared__ float tile[32][33];
    int n = blockIdx.z;
    const float* src = (n < 128) ? L : R;
    int nn = n & 127;
    int h = nn >> 1, b = nn & 1;
    int i = blockIdx.x * 32 + threadIdx.x;       // width (input-contiguous)
    int c = blockIdx.y * 32 + threadIdx.y;
    tile[threadIdx.y][threadIdx.x] = src[(((size_t)b * 128 + c) * 64 + h) * 192 + i];
    __syncthreads();
    int i2 = blockIdx.x * 32 + threadIdx.y;
    int c2 = blockIdx.y * 32 + threadIdx.x;
    feat[((size_t)i2 * 256 + n) * 128 + c2] = tile[threadIdx.x][threadIdx.y];
}

// ------------------------- LayerNorm ---------------------------------------
// one token per block (128 threads). Input row via window (n0,nW,nF); output compact.
__global__ void ln_kernel(const float* __restrict__ x, int n0, int nW, int nF,
                          const float* __restrict__ g, const float* __restrict__ b,
                          float* __restrict__ y)
{
    int t = blockIdx.x;
    int row = (t / nW) * nF + n0 + (t % nW);
    int c = threadIdx.x;
    float v = x[(size_t)row * 128 + c];
    float s = v, sq = v * v;
    #pragma unroll
    for (int o = 16; o > 0; o >>= 1) {
        s  += __shfl_xor_sync(0xffffffffu, s,  o);
        sq += __shfl_xor_sync(0xffffffffu, sq, o);
    }
    __shared__ float ss[4], ssq[4];
    int w = c >> 5, ln = c & 31;
    if (ln == 0) { ss[w] = s; ssq[w] = sq; }
    __syncthreads();
    s  = ss[0] + ss[1] + ss[2] + ss[3];
    sq = ssq[0] + ssq[1] + ssq[2] + ssq[3];
    float mean = s * (1.f / 128.f);
    float var  = sq * (1.f / 128.f) - mean * mean;
    y[(size_t)t * 128 + c] = (v - mean) * rsqrtf(var + 1e-5f) * g[c] + b[c];
}

// ------------------------- SGEMM (K=128 fixed) -----------------------------
// C[r, col] = sum_k A[map(r), k] * B[col, k] + bias[col]  (optionally += into C)
// A rows via window (aN0,aNW,aNF), pitch 128. C rows via window (cN0,cNW,cNF), pitch cPitch.
__global__ void sgemm(const float* __restrict__ A, int aN0, int aNW, int aNF,
                      const float* __restrict__ B, const float* __restrict__ bias,
                      float* __restrict__ C, int cN0, int cNW, int cNF, int cPitch,
                      int M, int N, int addRes)
{
    __shared__ float As[16][68];
    __shared__ float Bs[16][68];
    int tid = threadIdx.x;                 // 256 threads
    int tx = tid & 15, ty = tid >> 4;
    int rowBase = blockIdx.y * 64;
    int colBase = blockIdx.x * 64;

    float acc[4][4];
    #pragma unroll
    for (int i = 0; i < 4; i++)
        #pragma unroll
        for (int j = 0; j < 4; j++) acc[i][j] = 0.f;

    int lr = tid >> 2;                     // 0..63
    int lc = (tid & 3) * 4;                // 0,4,8,12
    int ar = rowBase + lr;
    const float* aRowPtr = nullptr;
    if (ar < M) {
        int arow = (ar / aNW) * aNF + aN0 + (ar % aNW);
        aRowPtr = A + (size_t)arow * 128;
    }
    int bc = colBase + lr;
    const float* bRowPtr = (bc < N) ? (B + (size_t)bc * 128) : nullptr;

    for (int kt = 0; kt < 8; kt++) {
        int k0 = kt * 16 + lc;
        float4 av = aRowPtr ? *(const float4*)(aRowPtr + k0) : make_float4(0, 0, 0, 0);
        float4 bv = bRowPtr ? *(const float4*)(bRowPtr + k0) : make_float4(0, 0, 0, 0);
        As[lc + 0][lr] = av.x; As[lc + 1][lr] = av.y; As[lc + 2][lr] = av.z; As[lc + 3][lr] = av.w;
        Bs[lc + 0][lr] = bv.x; Bs[lc + 1][lr] = bv.y; Bs[lc + 2][lr] = bv.z; Bs[lc + 3][lr] = bv.w;
        __syncthreads();
        #pragma unroll
        for (int k = 0; k < 16; k++) {
            float a0 = As[k][ty * 4 + 0], a1 = As[k][ty * 4 + 1];
            float a2 = As[k][ty * 4 + 2], a3 = As[k][ty * 4 + 3];
            float b0 = Bs[k][tx * 4 + 0], b1 = Bs[k][tx * 4 + 1];
            float b2 = Bs[k][tx * 4 + 2], b3 = Bs[k][tx * 4 + 3];
            acc[0][0] = fmaf(a0, b0, acc[0][0]); acc[0][1] = fmaf(a0, b1, acc[0][1]);
            acc[0][2] = fmaf(a0, b2, acc[0][2]); acc[0][3] = fmaf(a0, b3, acc[0][3]);
            acc[1][0] = fmaf(a1, b0, acc[1][0]); acc[1][1] = fmaf(a1, b1, acc[1][1]);
            acc[1][2] = fmaf(a1, b2, acc[1][2]); acc[1][3] = fmaf(a1, b3, acc[1][3]);
            acc[2][0] = fmaf(a2, b0, acc[2][0]); acc[2][1] = fmaf(a2, b1, acc[2][1]);
            acc[2][2] = fmaf(a2, b2, acc[2][2]); acc[2][3] = fmaf(a2, b3, acc[2][3]);
            acc[3][0] = fmaf(a3, b0, acc[3][0]); acc[3][1] = fmaf(a3, b1, acc[3][1]);
            acc[3][2] = fmaf(a3, b2, acc[3][2]); acc[3][3] = fmaf(a3, b3, acc[3][3]);
        }
        __syncthreads();
    }

    #pragma unroll
    for (int mi = 0; mi < 4; mi++) {
        int r = rowBase + ty * 4 + mi;
        if (r >= M) continue;
        int crow = (r / cNW) * cNF + cN0 + (r % cNW);
        float* cRow = C + (size_t)crow * cPitch;
        #pragma unroll
        for (int ni = 0; ni < 4; ni++) {
            int col = colBase + tx * 4 + ni;
            if (col >= N) continue;
            float v = acc[mi][ni] + bias[col];
            if (addRes) cRow[col] += v; else cRow[col] = v;
        }
    }
}

// ------------------------- fused rel-pos attention --------------------------
// one block per (n, e). scores s[i,j] = q_s[i]·k[j] + q_s[i]·pk[d] + k[j]·pq[d],
// d = 191-i+j (dSign>0) or 191+i-j (dSign<0). Online softmax + AV.
#define ATTN_SMEM ((192*33 + 32*193 + 192*33 + 32*384 + 32*384) * 4)

__global__ void attn_kernel(const float* __restrict__ qPtr, int qPitch, int qOff,
                            const float* __restrict__ kPtr, int kPitch, int kOff,
                            const float* __restrict__ vPtr, int vPitch, int vOff,
                            const float* __restrict__ proj,   // (383, 256): qr | kr
                            float* __restrict__ vo, int nB, int dSign)
{
    extern __shared__ float sm[];
    float* q_s = sm;                    // [192][33]
    float* kT  = q_s + 192 * 33;        // [32][193]  (k transposed)
    float* v_s = kT + 32 * 193;         // [192][33]
    float* pqT = v_s + 192 * 33;        // [32][384]  (q_r, scaled)
    float* pkT = pqT + 32 * 384;        // [32][384]  (k_r)

    int n = blockIdx.x;
    int e = blockIdx.y;
    int tid = threadIdx.x;
    const float scale = 0.17677669529663687f;   // 32^-0.5

    for (int idx = tid; idx < 192 * 32; idx += 256) {
        int i = idx >> 5, c = idx & 31;
        size_t base = (size_t)(i * nB + n);
        q_s[i * 33 + c] = qPtr[base * qPitch + qOff + e * 32 + c] * scale;
        kT[c * 193 + i] = kPtr[base * kPitch + kOff + e * 32 + c];
        v_s[i * 33 + c] = vPtr[base * vPitch + vOff + e * 32 + c];
    }
    for (int idx = tid; idx < 383 * 32; idx += 256) {
        int d = idx >> 5, c = idx & 31;
        pqT[c * 384 + d] = proj[(size_t)d * 256 + e * 32 + c] * scale;
        pkT[c * 384 + d] = proj[(size_t)d * 256 + 128 + e * 32 + c];
    }
    __syncthreads();

    int warp = tid >> 5, lane = tid & 31;
    for (int i = warp; i < 192; i += 8) {
        float qreg[32];
        #pragma unroll
        for (int c = 0; c < 32; c++) qreg[c] = q_s[i * 33 + c];
        float m = -1e30f, l = 0.f, acc = 0.f;
        #pragma unroll 1
        for (int jb = 0; jb < 6; jb++) {
            int j = jb * 32 + lane;
            int d = (dSign > 0) ? (191 - i + j) : (191 + i - j);
            float s = 0.f;
            #pragma unroll
            for (int c = 0; c < 32; c++) {
                float kv = kT[c * 193 + j];
                s = fmaf(qreg[c], kv, s);
                s = fmaf(qreg[c], pkT[c * 384 + d], s);
                s = fmaf(kv, pqT[c * 384 + d], s);
            }
            float mc = s;
            #pragma unroll
            for (int o = 16; o > 0; o >>= 1) mc = fmaxf(mc, __shfl_xor_sync(0xffffffffu, mc, o));
            float mn = fmaxf(m, mc);
            float corr = __expf(m - mn);
            float p = __expf(s - mn);
            float ls = p;
            #pragma unroll
            for (int o = 16; o > 0; o >>= 1) ls += __shfl_xor_sync(0xffffffffu, ls, o);
            l = l * corr + ls;
            acc *= corr;
            #pragma unroll
            for (int jj = 0; jj < 32; jj++) {
                float pj = __shfl_sync(0xffffffffu, p, jj);
                acc = fmaf(pj, v_s[(jb * 32 + jj) * 33 + lane], acc);
            }
            m = mn;
        }
        vo[(size_t)(i * nB + n) * 128 + e * 32 + lane] = acc / l;
    }
}

// ---------------------------------------------------------------------------
extern "C" void kernel_launch(void* const* d_in, const int* in_sizes, int n_in,
                              void* d_out, int out_size)
{
    (void)in_sizes; (void)n_in; (void)out_size;
    const float* feat_left  = (const float*)d_in[0];
    const float* feat_right = (const float*)d_in[1];
    const float* pos_enc    = (const float*)d_in[2];
    const float* s_iw = (const float*)d_in[3];
    const float* s_ib = (const float*)d_in[4];
    const float* s_ow = (const float*)d_in[5];
    const float* s_ob = (const float*)d_in[6];
    const float* s_g  = (const float*)d_in[7];
    const float* s_b  = (const float*)d_in[8];
    const float* c_iw = (const float*)d_in[9];
    const float* c_ib = (const float*)d_in[10];
    const float* c_ow = (const float*)d_in[11];
    const float* c_ob = (const float*)d_in[12];
    const float* c_g1 = (const float*)d_in[13];
    const float* c_b1 = (const float*)d_in[14];
    const float* c_g2 = (const float*)d_in[15];
    const float* c_b2 = (const float*)d_in[16];

    float* feat = (float*)d_out;

    float *ln_buf, *ln2_buf, *qkv, *vo, *projb;
    cudaGetSymbolAddress((void**)&ln_buf, g_ln);
    cudaGetSymbolAddress((void**)&ln2_buf, g_ln2);
    cudaGetSymbolAddress((void**)&qkv, g_qkv);
    cudaGetSymbolAddress((void**)&vo, g_vo);
    cudaGetSymbolAddress((void**)&projb, g_proj);
    float* projS = projb;
    float* projC = projb + 383 * 256;
    float* qb  = qkv;                         // cross q:  (w*128, 128)
    float* kvb = qkv + 192 * 128 * 128;       // cross kv: (w*128, 256)

    cudaFuncSetAttribute(attn_kernel, cudaFuncAttributeMaxDynamicSharedMemorySize, ATTN_SMEM);

    build_feat<<<dim3(6, 4, 256), dim3(32, 32)>>>(feat_left, feat_right, feat);

    for (int L = 0; L < 4; L++) {
        const float* siw = s_iw + (size_t)L * 384 * 128;
        const float* sib = s_ib + (size_t)L * 384;
        const float* sow = s_ow + (size_t)L * 128 * 128;
        const float* sob = s_ob + (size_t)L * 128;
        const float* ciw = c_iw + (size_t)L * 384 * 128;
        const float* cib = c_ib + (size_t)L * 384;
        const float* cow = c_ow + (size_t)L * 128 * 128;
        const float* cob = c_ob + (size_t)L * 128;

        // ---------------- self-attention ----------------
        ln_kernel<<<49152, 128>>>(feat, 0, 256, 256, s_g + L * 128, s_b + L * 128, ln_buf);
        // pos_enc projection through s_iw[:256] (replaces the w*w pe GEMM)
        sgemm<<<dim3(4, 6), 256>>>(pos_enc, 0, 383, 383, siw, sib,
                                   projS, 0, 383, 383, 256, 383, 256, 0);
        // qkv
        sgemm<<<dim3(6, 768), 256>>>(ln_buf, 0, 256, 256, siw, sib,
                                     qkv, 0, 256, 256, 384, 49152, 384, 0);
        attn_kernel<<<dim3(256, 4), 256, ATTN_SMEM>>>(qkv, 384, 0, qkv, 384, 128, qkv, 384, 256,
                                                      projS, vo, 256, +1);
        // out proj + residual into feat
        sgemm<<<dim3(2, 768), 256>>>(vo, 0, 256, 256, sow, sob,
                                     feat, 0, 256, 256, 128, 49152, 128, 1);

        // ---------------- cross-attention ----------------
        // fl2 | fr2 = LN(feat, c_g1, c_b1)  (same params both halves)
        ln_kernel<<<49152, 128>>>(feat, 0, 256, 256, c_g1 + L * 128, c_b1 + L * 128, ln_buf);
        sgemm<<<dim3(4, 6), 256>>>(pos_enc, 0, 383, 383, ciw, cib,
                                   projC, 0, 383, 383, 256, 383, 256, 0);

        // fr update: q from fr2 (n0=128), kv from fl2 (n0=0), flipped pos table (dSign=-1)
        sgemm<<<dim3(2, 384), 256>>>(ln_buf, 128, 128, 256, ciw, cib,
                                     qb, 0, 128, 128, 128, 24576, 128, 0);
        sgemm<<<dim3(4, 384), 256>>>(ln_buf, 0, 128, 256, ciw + 128 * 128, cib + 128,
                                     kvb, 0, 128, 128, 256, 24576, 256, 0);
        attn_kernel<<<dim3(128, 4), 256, ATTN_SMEM>>>(qb, 128, 0, kvb, 256, 0, kvb, 256, 128,
                                                      projC, vo, 128, -1);
        sgemm<<<dim3(2, 384), 256>>>(vo, 0, 128, 128, cow, cob,
                                     feat, 128, 128, 256, 128, 24576, 128, 1);

        // fr2n = LN(updated fr, c_g2, c_b2)
        ln_kernel<<<24576, 128>>>(feat, 128, 128, 256, c_g2 + L * 128, c_b2 + L * 128, ln2_buf);

        // fl update: q from fl2 (ln_buf n0=0), kv from fr2n (ln2_buf compact), normal pos table
        sgemm<<<dim3(2, 384), 256>>>(ln_buf, 0, 128, 256, ciw, cib,
                                     qb, 0, 128, 128, 128, 24576, 128, 0);
        sgemm<<<dim3(4, 384), 256>>>(ln2_buf, 0, 128, 128, ciw + 128 * 128, cib + 128,
                                     kvb, 0, 128, 128, 256, 24576, 256, 0);
        attn_kernel<<<dim3(128, 4), 256, ATTN_SMEM>>>(qb, 128, 0, kvb, 256, 0, kvb, 256, 128,
                                                      projC, vo, 128, +1);
        sgemm<<<dim3(2, 384), 256>>>(vo, 0, 128, 128, cow, cob,
                                     feat, 0, 128, 256, 128, 24576, 128, 1);
    }
}

// round 2
// speedup vs baseline: 2.0317x; 2.0317x over previous
#include <cuda_runtime.h>
#include <cuda_bf16.h>
#include <math.h>

// ---------------------------------------------------------------------------
// STTM: 4-layer transformer, w=192, C=128, NHEAD=4, hd=32
// feat layout: (w, n, C) row-major. Self: n in [0,256). fl: n<128, fr: n>=128.
// Rel-pos trick: project pos_enc (383 rows) once; gather with d = 191 -/+ (i-j).
// ---------------------------------------------------------------------------

#define W_ 192
#define CC 128

// ------------------------- device scratch ---------------------------------
__device__ float g_ln [W_*256*CC];
__device__ float g_ln2[W_*128*CC];
__device__ float g_qkv[W_*256*3*CC];
__device__ float g_vo [W_*256*CC];
__device__ float g_proj[2*383*256];

// ------------------------- build feat from inputs -------------------------
__global__ void build_feat(const float* __restrict__ L, const float* __restrict__ R,
                           float* __restrict__ feat)
{
    __shared__ float tile[32][33];
    int n = blockIdx.z;
    const float* src = (n < 128) ? L : R;
    int nn = n & 127;
    int h = nn >> 1, b = nn & 1;
    int i = blockIdx.x * 32 + threadIdx.x;
    int c = blockIdx.y * 32 + threadIdx.y;
    tile[threadIdx.y][threadIdx.x] = src[(((size_t)b * 128 + c) * 64 + h) * 192 + i];
    __syncthreads();
    int i2 = blockIdx.x * 32 + threadIdx.y;
    int c2 = blockIdx.y * 32 + threadIdx.x;
    feat[((size_t)i2 * 256 + n) * 128 + c2] = tile[threadIdx.x][threadIdx.y];
}

// ------------------------- LayerNorm: 1 warp per row, 4 rows/block ---------
__global__ void ln4_kernel(const float* __restrict__ x, int n0, int nW, int nF,
                           const float* __restrict__ g, const float* __restrict__ b,
                           float* __restrict__ y)
{
    int t = blockIdx.x * 4 + (threadIdx.x >> 5);
    int lane = threadIdx.x & 31;
    int row = (t / nW) * nF + n0 + (t % nW);
    float4 v = *(const float4*)(x + (size_t)row * 128 + lane * 4);
    float s  = v.x + v.y + v.z + v.w;
    float sq = v.x*v.x + v.y*v.y + v.z*v.z + v.w*v.w;
    #pragma unroll
    for (int o = 16; o > 0; o >>= 1) {
        s  += __shfl_xor_sync(0xffffffffu, s,  o);
        sq += __shfl_xor_sync(0xffffffffu, sq, o);
    }
    float mean = s * (1.f / 128.f);
    float var  = sq * (1.f / 128.f) - mean * mean;
    float inv = rsqrtf(var + 1e-5f);
    float4 gv = *(const float4*)(g + lane * 4);
    float4 bv = *(const float4*)(b + lane * 4);
    float4 o4;
    o4.x = (v.x - mean) * inv * gv.x + bv.x;
    o4.y = (v.y - mean) * inv * gv.y + bv.y;
    o4.z = (v.z - mean) * inv * gv.z + bv.z;
    o4.w = (v.w - mean) * inv * gv.w + bv.w;
    *(float4*)(y + (size_t)t * 128 + lane * 4) = o4;
}

// ------------------------- small SGEMM (64x64 tiles, bounds-checked) -------
__global__ void sgemm64(const float* __restrict__ A, int aN0, int aNW, int aNF,
                        const float* __restrict__ B, const float* __restrict__ bias,
                        float* __restrict__ C, int cN0, int cNW, int cNF, int cPitch,
                        int M, int N, int addRes)
{
    __shared__ float As[16][68];
    __shared__ float Bs[16][68];
    int tid = threadIdx.x;
    int tx = tid & 15, ty = tid >> 4;
    int rowBase = blockIdx.y * 64;
    int colBase = blockIdx.x * 64;

    float acc[4][4];
    #pragma unroll
    for (int i = 0; i < 4; i++)
        #pragma unroll
        for (int j = 0; j < 4; j++) acc[i][j] = 0.f;

    int lr = tid >> 2;
    int lc = (tid & 3) * 4;
    int ar = rowBase + lr;
    const float* aRowPtr = nullptr;
    if (ar < M) {
        int arow = (ar / aNW) * aNF + aN0 + (ar % aNW);
        aRowPtr = A + (size_t)arow * 128;
    }
    int bc = colBase + lr;
    const float* bRowPtr = (bc < N) ? (B + (size_t)bc * 128) : nullptr;

    for (int kt = 0; kt < 8; kt++) {
        int k0 = kt * 16 + lc;
        float4 av = aRowPtr ? *(const float4*)(aRowPtr + k0) : make_float4(0, 0, 0, 0);
        float4 bv = bRowPtr ? *(const float4*)(bRowPtr + k0) : make_float4(0, 0, 0, 0);
        As[lc + 0][lr] = av.x; As[lc + 1][lr] = av.y; As[lc + 2][lr] = av.z; As[lc + 3][lr] = av.w;
        Bs[lc + 0][lr] = bv.x; Bs[lc + 1][lr] = bv.y; Bs[lc + 2][lr] = bv.z; Bs[lc + 3][lr] = bv.w;
        __syncthreads();
        #pragma unroll
        for (int k = 0; k < 16; k++) {
            float a0 = As[k][ty * 4 + 0], a1 = As[k][ty * 4 + 1];
            float a2 = As[k][ty * 4 + 2], a3 = As[k][ty * 4 + 3];
            float b0 = Bs[k][tx * 4 + 0], b1 = Bs[k][tx * 4 + 1];
            float b2 = Bs[k][tx * 4 + 2], b3 = Bs[k][tx * 4 + 3];
            acc[0][0] = fmaf(a0, b0, acc[0][0]); acc[0][1] = fmaf(a0, b1, acc[0][1]);
            acc[0][2] = fmaf(a0, b2, acc[0][2]); acc[0][3] = fmaf(a0, b3, acc[0][3]);
            acc[1][0] = fmaf(a1, b0, acc[1][0]); acc[1][1] = fmaf(a1, b1, acc[1][1]);
            acc[1][2] = fmaf(a1, b2, acc[1][2]); acc[1][3] = fmaf(a1, b3, acc[1][3]);
            acc[2][0] = fmaf(a2, b0, acc[2][0]); acc[2][1] = fmaf(a2, b1, acc[2][1]);
            acc[2][2] = fmaf(a2, b2, acc[2][2]); acc[2][3] = fmaf(a2, b3, acc[2][3]);
            acc[3][0] = fmaf(a3, b0, acc[3][0]); acc[3][1] = fmaf(a3, b1, acc[3][1]);
            acc[3][2] = fmaf(a3, b2, acc[3][2]); acc[3][3] = fmaf(a3, b3, acc[3][3]);
        }
        __syncthreads();
    }

    #pragma unroll
    for (int mi = 0; mi < 4; mi++) {
        int r = rowBase + ty * 4 + mi;
        if (r >= M) continue;
        int crow = (r / cNW) * cNF + cN0 + (r % cNW);
        float* cRow = C + (size_t)crow * cPitch;
        #pragma unroll
        for (int ni = 0; ni < 4; ni++) {
            int col = colBase + tx * 4 + ni;
            if (col >= N) continue;
            float v = acc[mi][ni] + bias[col];
            if (addRes) cRow[col] += v; else cRow[col] = v;
        }
    }
}

// ------------------------- big SGEMM: 128x128 block, 8x8/thread, K=128 -----
// requires M % 128 == 0 (grid.y = M/128), N % 128 == 0 (grid.x = N/128).
__global__ void __launch_bounds__(256) sgemm128(
    const float* __restrict__ A, int aN0, int aNW, int aNF,
    const float* __restrict__ B, const float* __restrict__ bias,
    float* __restrict__ C, int cN0, int cNW, int cNF, int cPitch,
    int addRes)
{
    __shared__ float As[16][132];
    __shared__ float Bs[16][132];
    int tid = threadIdx.x;
    int tx = tid & 15, ty = tid >> 4;
    int rowBase = blockIdx.y * 128;
    int colBase = blockIdx.x * 128;

    float acc[8][8];
    #pragma unroll
    for (int i = 0; i < 8; i++)
        #pragma unroll
        for (int j = 0; j < 8; j++) acc[i][j] = 0.f;

    int lr = tid >> 1;
    int lk = (tid & 1) * 8;
    int ar = rowBase + lr;
    int arow = (ar / aNW) * aNF + aN0 + (ar % aNW);
    const float* aPtr = A + (size_t)arow * 128 + lk;
    const float* bPtr = B + (size_t)(colBase + lr) * 128 + lk;

    for (int kt = 0; kt < 8; kt++) {
        float4 a0 = *(const float4*)(aPtr + kt * 16);
        float4 a1 = *(const float4*)(aPtr + kt * 16 + 4);
        float4 b0 = *(const float4*)(bPtr + kt * 16);
        float4 b1 = *(const float4*)(bPtr + kt * 16 + 4);
        __syncthreads();
        As[lk + 0][lr] = a0.x; As[lk + 1][lr] = a0.y; As[lk + 2][lr] = a0.z; As[lk + 3][lr] = a0.w;
        As[lk + 4][lr] = a1.x; As[lk + 5][lr] = a1.y; As[lk + 6][lr] = a1.z; As[lk + 7][lr] = a1.w;
        Bs[lk + 0][lr] = b0.x; Bs[lk + 1][lr] = b0.y; Bs[lk + 2][lr] = b0.z; Bs[lk + 3][lr] = b0.w;
        Bs[lk + 4][lr] = b1.x; Bs[lk + 5][lr] = b1.y; Bs[lk + 6][lr] = b1.z; Bs[lk + 7][lr] = b1.w;
        __syncthreads();
        #pragma unroll
        for (int k = 0; k < 16; k++) {
            float4 A0 = *(const float4*)&As[k][ty * 8];
            float4 A1 = *(const float4*)&As[k][ty * 8 + 4];
            float4 B0 = *(const float4*)&Bs[k][tx * 8];
            float4 B1 = *(const float4*)&Bs[k][tx * 8 + 4];
            float ar8[8] = {A0.x, A0.y, A0.z, A0.w, A1.x, A1.y, A1.z, A1.w};
            float br8[8] = {B0.x, B0.y, B0.z, B0.w, B1.x, B1.y, B1.z, B1.w};
            #pragma unroll
            for (int i = 0; i < 8; i++)
                #pragma unroll
                for (int j = 0; j < 8; j++)
                    acc[i][j] = fmaf(ar8[i], br8[j], acc[i][j]);
        }
    }

    float4 bia0 = *(const float4*)(bias + colBase + tx * 8);
    float4 bia1 = *(const float4*)(bias + colBase + tx * 8 + 4);
    float bb[8] = {bia0.x, bia0.y, bia0.z, bia0.w, bia1.x, bia1.y, bia1.z, bia1.w};

    #pragma unroll
    for (int i = 0; i < 8; i++) {
        int r = rowBase + ty * 8 + i;
        int crow = (r / cNW) * cNF + cN0 + (r % cNW);
        float* cp = C + (size_t)crow * cPitch + colBase + tx * 8;
        float4 v0, v1;
        v0.x = acc[i][0] + bb[0]; v0.y = acc[i][1] + bb[1];
        v0.z = acc[i][2] + bb[2]; v0.w = acc[i][3] + bb[3];
        v1.x = acc[i][4] + bb[4]; v1.y = acc[i][5] + bb[5];
        v1.z = acc[i][6] + bb[6]; v1.w = acc[i][7] + bb[7];
        if (addRes) {
            float4 c0 = *(const float4*)cp;
            float4 c1 = *(const float4*)(cp + 4);
            v0.x += c0.x; v0.y += c0.y; v0.z += c0.z; v0.w += c0.w;
            v1.x += c1.x; v1.y += c1.y; v1.z += c1.z; v1.w += c1.w;
        }
        *(float4*)cp = v0;
        *(float4*)(cp + 4) = v1;
    }
}

// ------------------------- fused rel-pos attention (4x4 tiles) -------------
// block = (n, e). 384 threads = 12 warps, each warp owns 16 rows.
// s[i,j] = q[i]·k[j] + q[i]·pk[d] + k[j]·pq[d], d = 191 - DSIGN*(i - j).
#define ATTN_SMEM ((32*196*2 + 192*36 + 32*384*2) * 4)

template<int DSIGN>
__global__ void __launch_bounds__(384, 1) attn_kernel(
    const float* __restrict__ qPtr, int qPitch, int qOff,
    const float* __restrict__ kPtr, int kPitch, int kOff,
    const float* __restrict__ vPtr, int vPitch, int vOff,
    const float* __restrict__ proj, float* __restrict__ vo, int nB)
{
    extern __shared__ float sm[];
    float* qT  = sm;               // [32][196]  qT[c][i], pre-scaled
    float* kT  = qT  + 32 * 196;   // [32][196]
    float* v_s = kT  + 32 * 196;   // [192][36]
    float* pqT = v_s + 192 * 36;   // [32][384]  q_r, pre-scaled
    float* pkT = pqT + 32 * 384;   // [32][384]  k_r

    int n = blockIdx.x, e = blockIdx.y, tid = threadIdx.x;
    const float scale = 0.17677669529663687f;

    for (int idx = tid; idx < 192 * 32; idx += 384) {
        int i = idx >> 5, c = idx & 31;
        size_t base = (size_t)(i * nB + n);
        qT[c * 196 + i] = qPtr[base * qPitch + qOff + e * 32 + c] * scale;
        kT[c * 196 + i] = kPtr[base * kPitch + kOff + e * 32 + c];
        v_s[i * 36 + c] = vPtr[base * vPitch + vOff + e * 32 + c];
    }
    for (int idx = tid; idx < 383 * 32; idx += 384) {
        int d = idx >> 5, c = idx & 31;
        pqT[c * 384 + d] = proj[(size_t)d * 256 + e * 32 + c] * scale;
        pkT[c * 384 + d] = proj[(size_t)d * 256 + 128 + e * 32 + c];
    }
    __syncthreads();

    int warp = tid >> 5, lane = tid & 31;
    int rg = lane >> 3, jg = lane & 7;
    int i0 = warp * 16 + rg * 4;          // first of this thread's 4 rows

    float o[4][4];
    float m[4], l[4];
    #pragma unroll
    for (int di = 0; di < 4; di++) {
        m[di] = -1e30f; l[di] = 0.f;
        #pragma unroll
        for (int vc = 0; vc < 4; vc++) o[di][vc] = 0.f;
    }

    #pragma unroll 1
    for (int jt = 0; jt < 6; jt++) {
        int j0 = jt * 32 + jg * 4;        // first of this thread's 4 cols
        int pb = (DSIGN > 0) ? (188 - i0 + j0) : (188 + i0 - j0);   // multiple of 4, >=0

        float s[4][4];
        #pragma unroll
        for (int di = 0; di < 4; di++)
            #pragma unroll
            for (int dj = 0; dj < 4; dj++) s[di][dj] = 0.f;

        #pragma unroll
        for (int c = 0; c < 32; c++) {
            float4 qv = *(const float4*)&qT[c * 196 + i0];
            float4 kv = *(const float4*)&kT[c * 196 + j0];
            const float* pkb = &pkT[c * 384 + pb];
            const float* pqb = &pqT[c * 384 + pb];
            float4 pkA = *(const float4*)pkb;
            float4 pkB = *(const float4*)(pkb + 4);
            float4 pqA = *(const float4*)pqb;
            float4 pqB = *(const float4*)(pqb + 4);
            float qa[4] = {qv.x, qv.y, qv.z, qv.w};
            float ka[4] = {kv.x, kv.y, kv.z, kv.w};
            float pk8[8] = {pkA.x, pkA.y, pkA.z, pkA.w, pkB.x, pkB.y, pkB.z, pkB.w};
            float pq8[8] = {pqA.x, pqA.y, pqA.z, pqA.w, pqB.x, pqB.y, pqB.z, pqB.w};
            #pragma unroll
            for (int di = 0; di < 4; di++) {
                #pragma unroll
                for (int dj = 0; dj < 4; dj++) {
                    const int ix = (DSIGN > 0) ? (3 - di + dj) : (3 + di - dj);
                    float acc = s[di][dj];
                    acc = fmaf(qa[di], ka[dj], acc);
                    acc = fmaf(qa[di], pk8[ix], acc);
                    acc = fmaf(ka[dj], pq8[ix], acc);
                    s[di][dj] = acc;
                }
            }
        }

        // online softmax (row = rg rows; row segments live on 8 jg lanes)
        #pragma unroll
        for (int di = 0; di < 4; di++) {
            float mx = fmaxf(fmaxf(s[di][0], s[di][1]), fmaxf(s[di][2], s[di][3]));
            mx = fmaxf(mx, __shfl_xor_sync(0xffffffffu, mx, 1));
            mx = fmaxf(mx, __shfl_xor_sync(0xffffffffu, mx, 2));
            mx = fmaxf(mx, __shfl_xor_sync(0xffffffffu, mx, 4));
            float mn = fmaxf(m[di], mx);
            float corr = __expf(m[di] - mn);
            float rs = 0.f;
            #pragma unroll
            for (int dj = 0; dj < 4; dj++) {
                s[di][dj] = __expf(s[di][dj] - mn);
                rs += s[di][dj];
            }
            rs += __shfl_xor_sync(0xffffffffu, rs, 1);
            rs += __shfl_xor_sync(0xffffffffu, rs, 2);
            rs += __shfl_xor_sync(0xffffffffu, rs, 4);
            l[di] = l[di] * corr + rs;
            #pragma unroll
            for (int vc = 0; vc < 4; vc++) o[di][vc] *= corr;
            m[di] = mn;
        }

        // AV: o[di][vc] += P[row][j] * V[j][jg*4+vc]
        int jbase = jt * 32;
        #pragma unroll
        for (int j = 0; j < 32; j++) {
            int src = rg * 8 + (j >> 2);
            float4 vv = *(const float4*)&v_s[(jbase + j) * 36 + jg * 4];
            #pragma unroll
            for (int di = 0; di < 4; di++) {
                float pj = __shfl_sync(0xffffffffu, s[di][j & 3], src);
                o[di][0] = fmaf(pj, vv.x, o[di][0]);
                o[di][1] = fmaf(pj, vv.y, o[di][1]);
                o[di][2] = fmaf(pj, vv.z, o[di][2]);
                o[di][3] = fmaf(pj, vv.w, o[di][3]);
            }
        }
    }

    #pragma unroll
    for (int di = 0; di < 4; di++) {
        float inv = 1.0f / l[di];
        int ri = i0 + di;
        float4 ov;
        ov.x = o[di][0] * inv; ov.y = o[di][1] * inv;
        ov.z = o[di][2] * inv; ov.w = o[di][3] * inv;
        *(float4*)&vo[((size_t)(ri * nB + n)) * 128 + e * 32 + jg * 4] = ov;
    }
}

// ---------------------------------------------------------------------------
extern "C" void kernel_launch(void* const* d_in, const int* in_sizes, int n_in,
                              void* d_out, int out_size)
{
    (void)in_sizes; (void)n_in; (void)out_size;
    const float* feat_left  = (const float*)d_in[0];
    const float* feat_right = (const float*)d_in[1];
    const float* pos_enc    = (const float*)d_in[2];
    const float* s_iw = (const float*)d_in[3];
    const float* s_ib = (const float*)d_in[4];
    const float* s_ow = (const float*)d_in[5];
    const float* s_ob = (const float*)d_in[6];
    const float* s_g  = (const float*)d_in[7];
    const float* s_b  = (const float*)d_in[8];
    const float* c_iw = (const float*)d_in[9];
    const float* c_ib = (const float*)d_in[10];
    const float* c_ow = (const float*)d_in[11];
    const float* c_ob = (const float*)d_in[12];
    const float* c_g1 = (const float*)d_in[13];
    const float* c_b1 = (const float*)d_in[14];
    const float* c_g2 = (const float*)d_in[15];
    const float* c_b2 = (const float*)d_in[16];

    float* feat = (float*)d_out;

    float *ln_buf, *ln2_buf, *qkv, *vo, *projb;
    cudaGetSymbolAddress((void**)&ln_buf, g_ln);
    cudaGetSymbolAddress((void**)&ln2_buf, g_ln2);
    cudaGetSymbolAddress((void**)&qkv, g_qkv);
    cudaGetSymbolAddress((void**)&vo, g_vo);
    cudaGetSymbolAddress((void**)&projb, g_proj);
    float* projS = projb;
    float* projC = projb + 383 * 256;
    float* qb  = qkv;
    float* kvb = qkv + 192 * 128 * 128;

    cudaFuncSetAttribute(attn_kernel<1>,  cudaFuncAttributeMaxDynamicSharedMemorySize, ATTN_SMEM);
    cudaFuncSetAttribute(attn_kernel<-1>, cudaFuncAttributeMaxDynamicSharedMemorySize, ATTN_SMEM);

    build_feat<<<dim3(6, 4, 256), dim3(32, 32)>>>(feat_left, feat_right, feat);

    for (int L = 0; L < 4; L++) {
        const float* siw = s_iw + (size_t)L * 384 * 128;
        const float* sib = s_ib + (size_t)L * 384;
        const float* sow = s_ow + (size_t)L * 128 * 128;
        const float* sob = s_ob + (size_t)L * 128;
        const float* ciw = c_iw + (size_t)L * 384 * 128;
        const float* cib = c_ib + (size_t)L * 384;
        const float* cow = c_ow + (size_t)L * 128 * 128;
        const float* cob = c_ob + (size_t)L * 128;

        // ---------------- self-attention ----------------
        ln4_kernel<<<12288, 128>>>(feat, 0, 256, 256, s_g + L * 128, s_b + L * 128, ln_buf);
        sgemm64<<<dim3(4, 6), 256>>>(pos_enc, 0, 383, 383, siw, sib,
                                     projS, 0, 383, 383, 256, 383, 256, 0);
        sgemm128<<<dim3(3, 384), 256>>>(ln_buf, 0, 256, 256, siw, sib,
                                        qkv, 0, 256, 256, 384, 0);
        attn_kernel<1><<<dim3(256, 4), 384, ATTN_SMEM>>>(qkv, 384, 0, qkv, 384, 128,
                                                         qkv, 384, 256, projS, vo, 256);
        sgemm128<<<dim3(1, 384), 256>>>(vo, 0, 256, 256, sow, sob,
                                        feat, 0, 256, 256, 128, 1);

        // ---------------- cross-attention ----------------
        ln4_kernel<<<12288, 128>>>(feat, 0, 256, 256, c_g1 + L * 128, c_b1 + L * 128, ln_buf);
        sgemm64<<<dim3(4, 6), 256>>>(pos_enc, 0, 383, 383, ciw, cib,
                                     projC, 0, 383, 383, 256, 383, 256, 0);

        // fr update: q from fr2, kv from fl2, flipped table (DSIGN=-1)
        sgemm128<<<dim3(1, 192), 256>>>(ln_buf, 128, 128, 256, ciw, cib,
                                        qb, 0, 128, 128, 128, 0);
        sgemm128<<<dim3(2, 192), 256>>>(ln_buf, 0, 128, 256, ciw + 128 * 128, cib + 128,
                                        kvb, 0, 128, 128, 256, 0);
        attn_kernel<-1><<<dim3(128, 4), 384, ATTN_SMEM>>>(qb, 128, 0, kvb, 256, 0,
                                                          kvb, 256, 128, projC, vo, 128);
        sgemm128<<<dim3(1, 192), 256>>>(vo, 0, 128, 128, cow, cob,
                                        feat, 128, 128, 256, 128, 1);

        // fr2n = LN(updated fr)
        ln4_kernel<<<6144, 128>>>(feat, 128, 128, 256, c_g2 + L * 128, c_b2 + L * 128, ln2_buf);

        // fl update: q from fl2, kv from fr2n, normal table (DSIGN=+1)
        sgemm128<<<dim3(1, 192), 256>>>(ln_buf, 0, 128, 256, ciw, cib,
                                        qb, 0, 128, 128, 128, 0);
        sgemm128<<<dim3(2, 192), 256>>>(ln2_buf, 0, 128, 128, ciw + 128 * 128, cib + 128,
                                        kvb, 0, 128, 128, 256, 0);
        attn_kernel<1><<<dim3(128, 4), 384, ATTN_SMEM>>>(qb, 128, 0, kvb, 256, 0,
                                                         kvb, 256, 128, projC, vo, 128);
        sgemm128<<<dim3(1, 192), 256>>>(vo, 0, 128, 128, cow, cob,
                                        feat, 0, 128, 256, 128, 1);
    }
}